// round 1
// baseline (speedup 1.0000x reference)
#include <cuda_runtime.h>
#include <cstdint>

// COO SpMM: out[src[e], :] += att[e] * X[dst[e], :]
// N = out_size / 128 nodes, D = 128 features, E = in_sizes[1] edges.
//
// Strategy: warp per edge. Each lane handles one float4 (4 feats); 32 lanes
// cover D=128 exactly. Gather X[dst] is one coalesced 512B read (L2-resident:
// X is 51MB, fits in the 126MB L2). Scatter uses red.global.add.v4.f32
// (no-return vector atomic, sm_90+) -> 4x fewer L2 atomic ops than scalar.

#define D_FEAT 128
#define THREADS 256
#define WARPS_PER_BLOCK (THREADS / 32)

__global__ void zero_out_kernel(float4* __restrict__ out, int n4) {
    int i = blockIdx.x * blockDim.x + threadIdx.x;
    int stride = gridDim.x * blockDim.x;
    float4 z = make_float4(0.f, 0.f, 0.f, 0.f);
    for (; i < n4; i += stride) out[i] = z;
}

__global__ void spmm_kernel(const void* __restrict__ edges_raw,
                            const float* __restrict__ att,
                            const float4* __restrict__ X,
                            float* __restrict__ out,
                            int E) {
    // Detect edge dtype (int64 vs int32) once per block.
    // Node ids < 100000 << 2^31, so if int64, the high 32-bit word of every
    // value is 0. Check 3 high words -> false positive prob ~1e-15 for int32.
    __shared__ int s_is64;
    if (threadIdx.x == 0) {
        const int* w = (const int*)edges_raw;
        s_is64 = (w[1] == 0 && w[3] == 0 && w[5] == 0) ? 1 : 0;
    }
    __syncthreads();
    const int is64 = s_is64;

    int warp_in_block = threadIdx.x >> 5;
    int lane = threadIdx.x & 31;
    int e = blockIdx.x * WARPS_PER_BLOCK + warp_in_block;
    if (e >= E) return;

    long long src, dst;
    if (is64) {
        const long long* ed = (const long long*)edges_raw;
        src = ed[e];
        dst = ed[(long long)E + e];
    } else {
        const int* ed = (const int*)edges_raw;
        src = ed[e];
        dst = ed[(long long)E + e];
    }
    float a = __ldg(att + e);

    // Gather one float4 per lane: 32 lanes * 16B = 512B = full feature row.
    float4 v = __ldg(X + dst * (D_FEAT / 4) + lane);
    v.x *= a; v.y *= a; v.z *= a; v.w *= a;

    float* dstp = out + src * D_FEAT + lane * 4;
    asm volatile("red.global.add.v4.f32 [%0], {%1, %2, %3, %4};"
                 :: "l"(dstp), "f"(v.x), "f"(v.y), "f"(v.z), "f"(v.w)
                 : "memory");
}

extern "C" void kernel_launch(void* const* d_in, const int* in_sizes, int n_in,
                              void* d_out, int out_size) {
    const void* edges = d_in[0];               // (2, E) int32 or int64
    const float* att = (const float*)d_in[1];  // (E,)
    const float4* X = (const float4*)d_in[3];  // (N, 128) fp32
    float* out = (float*)d_out;                // (N, 128) fp32

    int E = in_sizes[1];
    int n4 = out_size / 4;

    zero_out_kernel<<<512, THREADS>>>((float4*)out, n4);

    int blocks = (E + WARPS_PER_BLOCK - 1) / WARPS_PER_BLOCK;
    spmm_kernel<<<blocks, THREADS>>>(edges, att, X, out, E);
}

// round 2
// speedup vs baseline: 2.6855x; 2.6855x over previous
#include <cuda_runtime.h>
#include <cstdint>

// COO SpMM via on-the-fly CSR (counting sort), then gather-accumulate.
// out[src[e], :] += att[e] * X[dst[e], :],  D = 128 fp32.
//
// R1 was REDG-issue-bound (~1.29 cyc/lane spread-addr * 32 lanes * 3.2M warps
// / 148 SMs ~= measured cycles). This version removes all float atomics:
//   1. histogram of src            (int atomics, cheap)
//   2. exclusive scan -> rowptr    (3 small kernels)
//   3. scatter packed (dst,att)    (int atomics for slots + 8B writes)
//   4. warp-per-node gather+FMA    (register accumulate, plain STG)

#define D4 32              // float4s per 128-float row
#define SCAN_BLK 1024
#define N_MAX 131072       // >= N+1 padded to SCAN_BLK
#define E_MAX 3276800      // >= E

__device__ int  g_is64;
__device__ int  g_count[N_MAX];               // histogram, then fill cursor
__device__ int  g_rowptr[N_MAX + 1];
__device__ int  g_blocksums[N_MAX / SCAN_BLK];
__device__ int2 g_edge[E_MAX];                // (dst, att bits) sorted by src

// ---- edge index fetch (int64 vs int32 detected at runtime) ----
__device__ __forceinline__ int edge_at(const void* edges, long long idx, int is64) {
    if (is64) return (int)((const long long*)edges)[idx];
    return ((const int*)edges)[idx];
}

__global__ void detect_kernel(const int* w) {
    if (threadIdx.x == 0) {
        // node ids << 2^31: if int64, high words are 0. int32 false-positive ~1e-15.
        g_is64 = (w[1] == 0 && w[3] == 0 && w[5] == 0) ? 1 : 0;
    }
}

__global__ void zero_counts_kernel(int npad) {
    int i = blockIdx.x * blockDim.x + threadIdx.x;
    if (i < npad) g_count[i] = 0;
}

__global__ void hist_kernel(const void* __restrict__ edges, int E) {
    const int is64 = g_is64;
    int stride = gridDim.x * blockDim.x;
    for (int e = blockIdx.x * blockDim.x + threadIdx.x; e < E; e += stride) {
        int s = edge_at(edges, e, is64);
        atomicAdd(&g_count[s], 1);
    }
}

// Per-block inclusive scan (Hillis-Steele); writes local exclusive + block sum.
__global__ void scan1_kernel() {
    __shared__ int sh[SCAN_BLK];
    int i = blockIdx.x * SCAN_BLK + threadIdx.x;
    int v = g_count[i];
    sh[threadIdx.x] = v;
    __syncthreads();
    #pragma unroll
    for (int off = 1; off < SCAN_BLK; off <<= 1) {
        int t = (threadIdx.x >= off) ? sh[threadIdx.x - off] : 0;
        __syncthreads();
        sh[threadIdx.x] += t;
        __syncthreads();
    }
    g_rowptr[i] = sh[threadIdx.x] - v;           // exclusive
    if (threadIdx.x == SCAN_BLK - 1) g_blocksums[blockIdx.x] = sh[threadIdx.x];
}

// Exclusive scan of <=128 block sums, single block of 128 threads.
__global__ void scan2_kernel(int nblocks) {
    __shared__ int sh[128];
    int v = (threadIdx.x < nblocks) ? g_blocksums[threadIdx.x] : 0;
    sh[threadIdx.x] = v;
    __syncthreads();
    #pragma unroll
    for (int off = 1; off < 128; off <<= 1) {
        int t = (threadIdx.x >= off) ? sh[threadIdx.x - off] : 0;
        __syncthreads();
        sh[threadIdx.x] += t;
        __syncthreads();
    }
    if (threadIdx.x < nblocks) g_blocksums[threadIdx.x] = sh[threadIdx.x] - v;
}

// Add block offsets; duplicate final rowptr into g_count as the fill cursor.
__global__ void scan3_kernel(int npad) {
    int i = blockIdx.x * blockDim.x + threadIdx.x;
    if (i < npad) {
        int r = g_rowptr[i] + g_blocksums[i / SCAN_BLK];
        g_rowptr[i] = r;
        g_count[i] = r;
    }
}

__global__ void scatter_kernel(const void* __restrict__ edges,
                               const float* __restrict__ att, int E) {
    const int is64 = g_is64;
    int stride = gridDim.x * blockDim.x;
    for (int e = blockIdx.x * blockDim.x + threadIdx.x; e < E; e += stride) {
        int s = edge_at(edges, e, is64);
        int d = edge_at(edges, (long long)E + e, is64);
        float a = __ldg(att + e);
        int p = atomicAdd(&g_count[s], 1);
        g_edge[p] = make_int2(d, __float_as_int(a));
    }
}

// Warp per node: lane l accumulates feature quad l. One uniform LDG.64 for
// edge meta + one coalesced 512B gather per edge; plain STG.128 at the end.
__global__ void spmm_csr_kernel(const float4* __restrict__ X,
                                float4* __restrict__ out, int N) {
    int lane = threadIdx.x & 31;
    int node = (blockIdx.x * blockDim.x + threadIdx.x) >> 5;
    if (node >= N) return;

    int e = g_rowptr[node];
    int end = g_rowptr[node + 1];
    float4 acc = make_float4(0.f, 0.f, 0.f, 0.f);

    for (; e + 2 <= end; e += 2) {
        int2 m0 = __ldg(&g_edge[e]);
        int2 m1 = __ldg(&g_edge[e + 1]);
        float4 v0 = __ldg(X + (long long)m0.x * D4 + lane);
        float4 v1 = __ldg(X + (long long)m1.x * D4 + lane);
        float a0 = __int_as_float(m0.y);
        float a1 = __int_as_float(m1.y);
        acc.x = fmaf(a0, v0.x, acc.x); acc.y = fmaf(a0, v0.y, acc.y);
        acc.z = fmaf(a0, v0.z, acc.z); acc.w = fmaf(a0, v0.w, acc.w);
        acc.x = fmaf(a1, v1.x, acc.x); acc.y = fmaf(a1, v1.y, acc.y);
        acc.z = fmaf(a1, v1.z, acc.z); acc.w = fmaf(a1, v1.w, acc.w);
    }
    if (e < end) {
        int2 m = __ldg(&g_edge[e]);
        float4 v = __ldg(X + (long long)m.x * D4 + lane);
        float a = __int_as_float(m.y);
        acc.x = fmaf(a, v.x, acc.x); acc.y = fmaf(a, v.y, acc.y);
        acc.z = fmaf(a, v.z, acc.z); acc.w = fmaf(a, v.w, acc.w);
    }

    out[(long long)node * D4 + lane] = acc;
}

extern "C" void kernel_launch(void* const* d_in, const int* in_sizes, int n_in,
                              void* d_out, int out_size) {
    const void* edges = d_in[0];               // (2, E) int32 or int64
    const float* att = (const float*)d_in[1];  // (E,)
    const float4* X = (const float4*)d_in[3];  // (N, 128) fp32
    float4* out = (float4*)d_out;

    int E = in_sizes[1];
    int N = out_size / 128;
    int npad = ((N + 1 + SCAN_BLK - 1) / SCAN_BLK) * SCAN_BLK;  // <= N_MAX
    int nsb = npad / SCAN_BLK;                                   // <= 128

    detect_kernel<<<1, 32>>>((const int*)edges);
    zero_counts_kernel<<<(npad + 255) / 256, 256>>>(npad);
    hist_kernel<<<2048, 256>>>(edges, E);
    scan1_kernel<<<nsb, SCAN_BLK>>>();
    scan2_kernel<<<1, 128>>>(nsb);
    scan3_kernel<<<(npad + 255) / 256, 256>>>(npad);
    scatter_kernel<<<2048, 256>>>(edges, att, E);

    int blocks = (N + 7) / 8;   // 8 warps (nodes) per 256-thread block
    spmm_csr_kernel<<<blocks, 256>>>(X, out, N);
}